// round 1
// baseline (speedup 1.0000x reference)
#include <cuda_runtime.h>
#include <math.h>

#define BN 32
#define NQ 1024
#define FD 128
#define MU_C 0.01f
#define LAM_C 2.0f
#define EPS_C 1e-15f
#define ISQN (1.0f/32.0f)   // 1/sqrt(N)

// ---- scratch (device globals; no runtime allocation allowed) ----
static __device__ float g_D0[(size_t)BN * NQ * NQ];   // 128 MB ping
static __device__ float g_D1[(size_t)BN * NQ * NQ];   // 128 MB pong
static __device__ float g_dflat[BN * NQ];
static __device__ float g_d2[BN * NQ];
static __device__ float g_u[BN * NQ];
static __device__ float g_uod[BN * NQ];
static __device__ float g_s0[BN * NQ];
static __device__ float g_s1[BN * NQ];
static __device__ float g_rdu[BN * NQ];
static __device__ float g_rduod[BN * NQ];
static __device__ float g_rs0[BN * NQ];
static __device__ float g_rs1[BN * NQ];
static __device__ float g_A[BN * NQ];
static __device__ float g_kw[BN];
static __device__ float g_mc[BN];
static __device__ float g_or[BN];

// ---- K1: per-row degree + softmax(s) + u + uod. 1 warp per row. ----
__global__ void k1_rows(const float* __restrict__ adj, const float* __restrict__ s) {
    int row = blockIdx.x * 8 + (threadIdx.x >> 5);
    int l = threadIdx.x & 31;
    const float4* r4 = (const float4*)(adj + (size_t)row * NQ);
    float sum = 0.f;
    #pragma unroll 4
    for (int t = l; t < NQ / 4; t += 32) {
        float4 v = r4[t];
        sum += (v.x + v.y) + (v.z + v.w);
    }
    #pragma unroll
    for (int o = 16; o; o >>= 1) sum += __shfl_xor_sync(0xffffffffu, sum, o);
    if (l == 0) {
        float d2 = sqrtf(sum + EPS_C) + EPS_C;
        float a = s[row * 2 + 0], bb = s[row * 2 + 1];
        float mx = fmaxf(a, bb);
        float e0 = __expf(a - mx), e1 = __expf(bb - mx);
        float inv = 1.f / (e0 + e1);
        float uu = (bb > a) ? -ISQN : ISQN;  // argmax==1 -> -1/sqrt(N)
        g_dflat[row] = sum;
        g_d2[row] = d2;
        g_u[row] = uu;
        g_uod[row] = uu / d2;
        g_s0[row] = e0 * inv;
        g_s1[row] = e1 * inv;
    }
}

// ---- K2: per-row dot products with u, uod, s0, s1. 1 warp per row. ----
__global__ void k2_rowdots(const float* __restrict__ adj) {
    __shared__ float su[NQ], suod[NQ], ss0[NQ], ss1[NQ];
    int b = blockIdx.x >> 7;  // 128 blocks per batch (8 rows/block)
    int row = blockIdx.x * 8 + (threadIdx.x >> 5);
    int l = threadIdx.x & 31;
    int base = b * NQ;
    for (int t = threadIdx.x; t < NQ; t += 256) {
        su[t] = g_u[base + t];
        suod[t] = g_uod[base + t];
        ss0[t] = g_s0[base + t];
        ss1[t] = g_s1[base + t];
    }
    __syncthreads();
    const float4* r4 = (const float4*)(adj + (size_t)row * NQ);
    float au = 0.f, auo = 0.f, a0 = 0.f, a1 = 0.f;
    #pragma unroll 4
    for (int t = l; t < NQ / 4; t += 32) {
        float4 v = r4[t];
        int j = 4 * t;
        au  += v.x * su[j]   + v.y * su[j+1]   + v.z * su[j+2]   + v.w * su[j+3];
        auo += v.x * suod[j] + v.y * suod[j+1] + v.z * suod[j+2] + v.w * suod[j+3];
        a0  += v.x * ss0[j]  + v.y * ss0[j+1]  + v.z * ss0[j+2]  + v.w * ss0[j+3];
        a1  += v.x * ss1[j]  + v.y * ss1[j+1]  + v.z * ss1[j+2]  + v.w * ss1[j+3];
    }
    #pragma unroll
    for (int o = 16; o; o >>= 1) {
        au  += __shfl_xor_sync(0xffffffffu, au, o);
        auo += __shfl_xor_sync(0xffffffffu, auo, o);
        a0  += __shfl_xor_sync(0xffffffffu, a0, o);
        a1  += __shfl_xor_sync(0xffffffffu, a1, o);
    }
    if (l == 0) {
        g_rdu[row] = au;
        g_rduod[row] = auo;
        g_rs0[row] = a0;
        g_rs1[row] = a1;
    }
}

// ---- K3: per-batch scalar reductions + A vector + out_adj + per-batch losses ----
__global__ void k3_batch(float* __restrict__ oadj) {
    int b = blockIdx.x, tid = threadIdx.x;
    int base = b * NQ;
    float p[13];
    #pragma unroll
    for (int q = 0; q < 13; q++) p[q] = 0.f;
    for (int n = tid; n < NQ; n += 256) {
        float df = g_dflat[base + n], d2 = g_d2[base + n];
        float uu = g_u[base + n],     uo = g_uod[base + n];
        float a0 = g_s0[base + n],    a1 = g_s1[base + n];
        float ru = g_rdu[base + n],   ruo = g_rduod[base + n];
        float r0 = g_rs0[base + n],   r1 = g_rs1[base + n];
        p[0] += uu * ruo;          // a_scal
        p[1] += uo * ru;           // s_scal
        p[2] += df * uo * uo;      // num term 1
        p[3] += uo * ruo;          // num term 2
        p[4] += d2 * d2;           // den * N
        p[5] += a0 * r0;           // out_adj[0][0]
        p[6] += a0 * r1;           // out_adj[0][1]
        p[7] += a1 * r0;           // out_adj[1][0]
        p[8] += a1 * r1;           // out_adj[1][1]
        p[9] += (a0 * a0 + a1 * a1) * df;  // mincut_den
        p[10] += a0 * a0;          // ss00
        p[11] += a0 * a1;          // ss01
        p[12] += a1 * a1;          // ss11
    }
    __shared__ float red[13][8];
    int w = tid >> 5, l = tid & 31;
    #pragma unroll
    for (int q = 0; q < 13; q++) {
        float t = p[q];
        #pragma unroll
        for (int o = 16; o; o >>= 1) t += __shfl_xor_sync(0xffffffffu, t, o);
        if (l == 0) red[q][w] = t;
    }
    __syncthreads();
    __shared__ float s_kA;
    if (tid == 0) {
        float tot[13];
        #pragma unroll
        for (int q = 0; q < 13; q++) {
            float t = 0.f;
            #pragma unroll
            for (int j = 0; j < 8; j++) t += red[q][j];
            tot[q] = t;
        }
        float c = tot[0] + tot[1];
        float num = tot[2] - tot[3];
        float den = tot[4] * (1.0f / NQ);
        float f = NQ * fabsf(num / (den + EPS_C));
        s_kA = -2.0f * LAM_C * f * c;
        g_kw[b] = -4.0f * LAM_C * f;
        oadj[b * 4 + 0] = tot[5];
        oadj[b * 4 + 1] = tot[6];
        oadj[b * 4 + 2] = tot[7];
        oadj[b * 4 + 3] = tot[8];
        g_mc[b] = -((tot[5] + tot[8]) / tot[9]);
        float ss00 = tot[10], ss01 = tot[11], ss11 = tot[12];
        float nrm = sqrtf(ss00 * ss00 + 2.f * ss01 * ss01 + ss11 * ss11);
        float isq = 0.70710678118654752f;
        float d00 = ss00 / nrm - isq;
        float d01 = ss01 / nrm;
        float d11 = ss11 / nrm - isq;
        g_or[b] = sqrtf(d00 * d00 + 2.f * d01 * d01 + d11 * d11);
    }
    __syncthreads();
    float kA = s_kA;
    for (int n = tid; n < NQ; n += 256) {
        float df = g_dflat[base + n], d2 = g_d2[base + n];
        g_A[base + n] = kA * (-0.5f * d2 / (df + EPS_C));  // A[i] = kA * dder[i]
    }
}

// ---- K5: means over batches ----
__global__ void k5_losses(float* __restrict__ mo) {
    if (threadIdx.x == 0) {
        float m = 0.f, o = 0.f;
        for (int b = 0; b < BN; b++) { m += g_mc[b]; o += g_or[b]; }
        mo[0] = m * (1.f / BN);
        mo[1] = o * (1.f / BN);
    }
}

// ---- K4: pooled features out[b,k,f] = sum_n s[n,k] x[n,f] ----
__global__ void k4_out(const float* __restrict__ x, float* __restrict__ outp) {
    int b = blockIdx.x;
    int f = threadIdx.x & 127;
    int sl = threadIdx.x >> 7;  // 0..3
    int base = b * NQ;
    float acc0 = 0.f, acc1 = 0.f;
    for (int n = sl; n < NQ; n += 4) {
        float xv = x[((size_t)(base + n)) * FD + f];
        acc0 += g_s0[base + n] * xv;
        acc1 += g_s1[base + n] * xv;
    }
    __shared__ float red[2][4][128];
    red[0][sl][f] = acc0;
    red[1][sl][f] = acc1;
    __syncthreads();
    if (sl == 0) {
        float t0 = red[0][0][f] + red[0][1][f] + red[0][2][f] + red[0][3][f];
        float t1 = red[1][0][f] + red[1][1][f] + red[1][2][f] + red[1][3][f];
        outp[(b * 2 + 0) * FD + f] = t0;
        outp[(b * 2 + 1) * FD + f] = t1;
    }
}

// ---- Iteration kernel: one projected-gradient + row-softmax step ----
// State tracked as D = Ac - adj (D0 = 0 so iter 1 reads only adj).
// Z[i,j] = adj[i,j] + D[i,j] - MU*(2(D[i,j]+D[j,i]) + A[i]+A[j]+kw*V[i]*V[j])
// diag:   Z[i,i] = adj+D - MU*(2D[i,i] + A[i] + 0.5*kw*V[i]^2)
// Ac_new = rowsoftmax(Z) * adj;  D_new = Ac_new - adj  (iter 5 writes Ac).
#define ITER_SMEM ((32 * NQ + 2 * NQ + 2 * 32 * 33) * 4)

__global__ __launch_bounds__(1024, 1)
void iter_kernel(const float* __restrict__ adj, int it, float* __restrict__ acOut) {
    extern __shared__ float sm[];
    float* Zs = sm;              // [32][1024]
    float* As = sm + 32 * NQ;    // [1024]
    float* Vs = As + NQ;         // [1024]
    float* Dc = Vs + NQ;         // double-buffered [32][33]

    int b = blockIdx.y;
    int i0 = blockIdx.x * 32;
    int tid = threadIdx.x, w = tid >> 5, l = tid & 31;
    size_t mb = (size_t)b * NQ * NQ;
    const float* adjb = adj + mb;
    const float* Db = (it == 1) ? nullptr : (((it & 1) == 0 ? g_D0 : g_D1) + mb);
    float* Ob = (it == 5) ? (acOut + mb) : (((it & 1) ? g_D0 : g_D1) + mb);

    As[tid] = g_A[b * NQ + tid];
    Vs[tid] = g_uod[b * NQ + tid];
    float kw = g_kw[b];
    int i = i0 + w;
    const float* arow = adjb + (size_t)i * NQ;
    const float* drow = Db ? (Db + (size_t)i * NQ) : nullptr;
    if (Db) Dc[w * 33 + l] = Db[(size_t)w * NQ + i0 + l];  // prologue: j-tile 0
    __syncthreads();

    float a_i = As[i], v_i = Vs[i];
    float wv_i = kw * v_i;
    float diagv = a_i + 0.5f * wv_i * v_i;
    float m = -3.4e38f;
    float* zr = Zs + w * NQ;

    for (int t = 0; t < 32; ++t) {
        int jc = t << 5;
        int cur = (t & 1) * 1056, nxt = 1056 - cur;
        if (Db && t < 31)
            Dc[nxt + w * 33 + l] = Db[(size_t)(jc + 32 + w) * NQ + i0 + l];
        int j = jc + l;
        float aij = arow[j];
        float z;
        if (Db) {
            float dij = drow[j];
            float dji = Dc[cur + l * 33 + w];
            float gs = a_i + As[j] + wv_i * Vs[j];
            z = aij + dij - MU_C * (2.f * (dij + dji) + gs);
            if (j == i) z = aij + dij - MU_C * (2.f * dij + diagv);
        } else {
            float gs = a_i + As[j] + wv_i * Vs[j];
            z = aij - MU_C * gs;
            if (j == i) z = aij - MU_C * diagv;
        }
        zr[j] = z;
        m = fmaxf(m, z);
        __syncthreads();
    }

    #pragma unroll
    for (int o = 16; o; o >>= 1) m = fmaxf(m, __shfl_xor_sync(0xffffffffu, m, o));

    float4* zr4 = (float4*)zr;
    float ssum = 0.f;
    #pragma unroll 4
    for (int t = l; t < NQ / 4; t += 32) {
        float4 z4 = zr4[t];
        z4.x = __expf(z4.x - m);
        z4.y = __expf(z4.y - m);
        z4.z = __expf(z4.z - m);
        z4.w = __expf(z4.w - m);
        zr4[t] = z4;
        ssum += (z4.x + z4.y) + (z4.z + z4.w);
    }
    #pragma unroll
    for (int o = 16; o; o >>= 1) ssum += __shfl_xor_sync(0xffffffffu, ssum, o);
    float rinv = 1.f / ssum;

    const float4* ar4 = (const float4*)arow;
    float4* or4 = (float4*)(Ob + (size_t)i * NQ);
    bool wAc = (it == 5);
    #pragma unroll 4
    for (int t = l; t < NQ / 4; t += 32) {
        float4 z4 = zr4[t], a4 = ar4[t], r;
        if (wAc) {
            r.x = z4.x * rinv * a4.x;
            r.y = z4.y * rinv * a4.y;
            r.z = z4.z * rinv * a4.z;
            r.w = z4.w * rinv * a4.w;
        } else {  // D_new = softmax*adj - adj
            r.x = fmaf(z4.x * rinv, a4.x, -a4.x);
            r.y = fmaf(z4.y * rinv, a4.y, -a4.y);
            r.z = fmaf(z4.z * rinv, a4.z, -a4.z);
            r.w = fmaf(z4.w * rinv, a4.w, -a4.w);
        }
        or4[t] = r;
    }
}

extern "C" void kernel_launch(void* const* d_in, const int* in_sizes, int n_in,
                              void* d_out, int out_size) {
    const float* x   = (const float*)d_in[0];
    const float* adj = (const float*)d_in[1];
    const float* s   = (const float*)d_in[2];
    float* out = (float*)d_out;

    // output layout: out[32,2,128] | Ac[32,1024,1024] | out_adj[32,2,2] | mincut | ortho
    const size_t AC_OFF   = (size_t)BN * 2 * FD;                 // 8192
    const size_t OADJ_OFF = AC_OFF + (size_t)BN * NQ * NQ;       // 33562624
    const size_t MC_OFF   = OADJ_OFF + (size_t)BN * 4;           // 33562752

    cudaFuncSetAttribute(iter_kernel, cudaFuncAttributeMaxDynamicSharedMemorySize,
                         ITER_SMEM);

    k1_rows<<<BN * NQ / 8, 256>>>(adj, s);
    k2_rowdots<<<BN * NQ / 8, 256>>>(adj);
    k3_batch<<<BN, 256>>>(out + OADJ_OFF);
    k5_losses<<<1, 32>>>(out + MC_OFF);
    k4_out<<<BN, 512>>>(x, out);

    dim3 g(NQ / 32, BN);
    for (int it = 1; it <= 5; ++it)
        iter_kernel<<<g, 1024, ITER_SMEM>>>(adj, it, out + AC_OFF);
}

// round 3
// speedup vs baseline: 2.1572x; 2.1572x over previous
#include <cuda_runtime.h>
#include <math.h>

#define BN 32
#define NQ 1024
#define FD 128
#define MU_C 0.01f
#define LAM_C 2.0f
#define EPS_C 1e-15f
#define ISQN (1.0f/32.0f)   // 1/sqrt(N)

// ---- scratch (device globals; no runtime allocation allowed) ----
static __device__ float g_D0[(size_t)BN * NQ * NQ];   // 128 MB ping
static __device__ float g_D1[(size_t)BN * NQ * NQ];   // 128 MB pong
static __device__ float g_dflat[BN * NQ];
static __device__ float g_d2[BN * NQ];
static __device__ float g_u[BN * NQ];
static __device__ float g_uod[BN * NQ];
static __device__ float g_s0[BN * NQ];
static __device__ float g_s1[BN * NQ];
static __device__ float g_rdu[BN * NQ];
static __device__ float g_rduod[BN * NQ];
static __device__ float g_rs0[BN * NQ];
static __device__ float g_rs1[BN * NQ];
static __device__ float g_A[BN * NQ];
static __device__ float g_kw[BN];
static __device__ float g_mc[BN];
static __device__ float g_or[BN];

// ---- K1: per-row degree + softmax(s) + u + uod. 1 warp per row. ----
__global__ void k1_rows(const float* __restrict__ adj, const float* __restrict__ s) {
    int row = blockIdx.x * 8 + (threadIdx.x >> 5);
    int l = threadIdx.x & 31;
    const float4* r4 = (const float4*)(adj + (size_t)row * NQ);
    float sum = 0.f;
    #pragma unroll 4
    for (int t = l; t < NQ / 4; t += 32) {
        float4 v = r4[t];
        sum += (v.x + v.y) + (v.z + v.w);
    }
    #pragma unroll
    for (int o = 16; o; o >>= 1) sum += __shfl_xor_sync(0xffffffffu, sum, o);
    if (l == 0) {
        float d2 = sqrtf(sum + EPS_C) + EPS_C;
        float a = s[row * 2 + 0], bb = s[row * 2 + 1];
        float mx = fmaxf(a, bb);
        float e0 = __expf(a - mx), e1 = __expf(bb - mx);
        float inv = 1.f / (e0 + e1);
        float uu = (bb > a) ? -ISQN : ISQN;  // argmax==1 -> -1/sqrt(N)
        g_dflat[row] = sum;
        g_d2[row] = d2;
        g_u[row] = uu;
        g_uod[row] = uu / d2;
        g_s0[row] = e0 * inv;
        g_s1[row] = e1 * inv;
    }
}

// ---- K2: per-row dot products with u, uod, s0, s1. 1 warp per row. ----
__global__ void k2_rowdots(const float* __restrict__ adj) {
    __shared__ float su[NQ], suod[NQ], ss0[NQ], ss1[NQ];
    int b = blockIdx.x >> 7;  // 128 blocks per batch (8 rows/block)
    int row = blockIdx.x * 8 + (threadIdx.x >> 5);
    int l = threadIdx.x & 31;
    int base = b * NQ;
    for (int t = threadIdx.x; t < NQ; t += 256) {
        su[t] = g_u[base + t];
        suod[t] = g_uod[base + t];
        ss0[t] = g_s0[base + t];
        ss1[t] = g_s1[base + t];
    }
    __syncthreads();
    const float4* r4 = (const float4*)(adj + (size_t)row * NQ);
    float au = 0.f, auo = 0.f, a0 = 0.f, a1 = 0.f;
    #pragma unroll 4
    for (int t = l; t < NQ / 4; t += 32) {
        float4 v = r4[t];
        int j = 4 * t;
        au  += v.x * su[j]   + v.y * su[j+1]   + v.z * su[j+2]   + v.w * su[j+3];
        auo += v.x * suod[j] + v.y * suod[j+1] + v.z * suod[j+2] + v.w * suod[j+3];
        a0  += v.x * ss0[j]  + v.y * ss0[j+1]  + v.z * ss0[j+2]  + v.w * ss0[j+3];
        a1  += v.x * ss1[j]  + v.y * ss1[j+1]  + v.z * ss1[j+2]  + v.w * ss1[j+3];
    }
    #pragma unroll
    for (int o = 16; o; o >>= 1) {
        au  += __shfl_xor_sync(0xffffffffu, au, o);
        auo += __shfl_xor_sync(0xffffffffu, auo, o);
        a0  += __shfl_xor_sync(0xffffffffu, a0, o);
        a1  += __shfl_xor_sync(0xffffffffu, a1, o);
    }
    if (l == 0) {
        g_rdu[row] = au;
        g_rduod[row] = auo;
        g_rs0[row] = a0;
        g_rs1[row] = a1;
    }
}

// ---- K3: per-batch scalar reductions + A vector + out_adj + per-batch losses ----
__global__ void k3_batch(float* __restrict__ oadj) {
    int b = blockIdx.x, tid = threadIdx.x;
    int base = b * NQ;
    float p[13];
    #pragma unroll
    for (int q = 0; q < 13; q++) p[q] = 0.f;
    for (int n = tid; n < NQ; n += 256) {
        float df = g_dflat[base + n], d2 = g_d2[base + n];
        float uu = g_u[base + n],     uo = g_uod[base + n];
        float a0 = g_s0[base + n],    a1 = g_s1[base + n];
        float ru = g_rdu[base + n],   ruo = g_rduod[base + n];
        float r0 = g_rs0[base + n],   r1 = g_rs1[base + n];
        p[0] += uu * ruo;          // a_scal
        p[1] += uo * ru;           // s_scal
        p[2] += df * uo * uo;      // num term 1
        p[3] += uo * ruo;          // num term 2
        p[4] += d2 * d2;           // den * N
        p[5] += a0 * r0;           // out_adj[0][0]
        p[6] += a0 * r1;           // out_adj[0][1]
        p[7] += a1 * r0;           // out_adj[1][0]
        p[8] += a1 * r1;           // out_adj[1][1]
        p[9] += (a0 * a0 + a1 * a1) * df;  // mincut_den
        p[10] += a0 * a0;          // ss00
        p[11] += a0 * a1;          // ss01
        p[12] += a1 * a1;          // ss11
    }
    __shared__ float red[13][8];
    int w = tid >> 5, l = tid & 31;
    #pragma unroll
    for (int q = 0; q < 13; q++) {
        float t = p[q];
        #pragma unroll
        for (int o = 16; o; o >>= 1) t += __shfl_xor_sync(0xffffffffu, t, o);
        if (l == 0) red[q][w] = t;
    }
    __syncthreads();
    __shared__ float s_kA;
    if (tid == 0) {
        float tot[13];
        #pragma unroll
        for (int q = 0; q < 13; q++) {
            float t = 0.f;
            #pragma unroll
            for (int j = 0; j < 8; j++) t += red[q][j];
            tot[q] = t;
        }
        float c = tot[0] + tot[1];
        float num = tot[2] - tot[3];
        float den = tot[4] * (1.0f / NQ);
        float f = NQ * fabsf(num / (den + EPS_C));
        s_kA = -2.0f * LAM_C * f * c;
        g_kw[b] = -4.0f * LAM_C * f;
        oadj[b * 4 + 0] = tot[5];
        oadj[b * 4 + 1] = tot[6];
        oadj[b * 4 + 2] = tot[7];
        oadj[b * 4 + 3] = tot[8];
        g_mc[b] = -((tot[5] + tot[8]) / tot[9]);
        float ss00 = tot[10], ss01 = tot[11], ss11 = tot[12];
        float nrm = sqrtf(ss00 * ss00 + 2.f * ss01 * ss01 + ss11 * ss11);
        float isq = 0.70710678118654752f;
        float d00 = ss00 / nrm - isq;
        float d01 = ss01 / nrm;
        float d11 = ss11 / nrm - isq;
        g_or[b] = sqrtf(d00 * d00 + 2.f * d01 * d01 + d11 * d11);
    }
    __syncthreads();
    float kA = s_kA;
    for (int n = tid; n < NQ; n += 256) {
        float df = g_dflat[base + n], d2 = g_d2[base + n];
        g_A[base + n] = kA * (-0.5f * d2 / (df + EPS_C));  // A[i] = kA * dder[i]
    }
}

// ---- K5: means over batches ----
__global__ void k5_losses(float* __restrict__ mo) {
    if (threadIdx.x == 0) {
        float m = 0.f, o = 0.f;
        for (int b = 0; b < BN; b++) { m += g_mc[b]; o += g_or[b]; }
        mo[0] = m * (1.f / BN);
        mo[1] = o * (1.f / BN);
    }
}

// ---- K4: pooled features out[b,k,f] = sum_n s[n,k] x[n,f] ----
__global__ void k4_out(const float* __restrict__ x, float* __restrict__ outp) {
    int b = blockIdx.x;
    int f = threadIdx.x & 127;
    int sl = threadIdx.x >> 7;  // 0..3
    int base = b * NQ;
    float acc0 = 0.f, acc1 = 0.f;
    for (int n = sl; n < NQ; n += 4) {
        float xv = x[((size_t)(base + n)) * FD + f];
        acc0 += g_s0[base + n] * xv;
        acc1 += g_s1[base + n] * xv;
    }
    __shared__ float red[2][4][128];
    red[0][sl][f] = acc0;
    red[1][sl][f] = acc1;
    __syncthreads();
    if (sl == 0) {
        float t0 = red[0][0][f] + red[0][1][f] + red[0][2][f] + red[0][3][f];
        float t1 = red[1][0][f] + red[1][1][f] + red[1][2][f] + red[1][3][f];
        outp[(b * 2 + 0) * FD + f] = t0;
        outp[(b * 2 + 1) * FD + f] = t1;
    }
}

// ---- Iteration kernel (v2): 2 barriers total, z in registers, high MLP ----
// State D = Ac - adj (D0 = 0 so iter 1 reads only adj).
// Z[i,j] = adj[i,j] + D[i,j] - MU*(2(D[i,j]+D[j,i]) + A[i]+A[j]+kw*V[i]*V[j])
// diag:   Z[i,i] = adj+D - MU*(2D[i,i] + A[i] + 0.5*kw*V[i]^2)
// Ac_new = rowsoftmax(Z) * adj;  D_new = Ac_new - adj  (iter 5 writes Ac).
//
// CTA = 256 threads = 8 warps = 8 rows (strip width 8). 2 CTAs/SM.
// Phase 1: stage transposed strip D[0:1024, i0:i0+8] into smem (pitch 9,
//          conflict-free). ONE barrier.
// Phase 2: warp w owns row i0+w; lane holds 32 z-values in registers;
//          max/exp/sum via warp shuffles only. No further barriers.
#define SW 8   // strip width (rows per CTA)

__global__ __launch_bounds__(256, 2)
void iter_kernel(const float* __restrict__ adj, int it, float* __restrict__ acOut) {
    __shared__ float Zt[NQ * (SW + 1)];   // Zt[j*(SW+1)+c] = D[j][i0+c]
    __shared__ float As[NQ], Vs[NQ];

    int b = blockIdx.y;
    int i0 = blockIdx.x * SW;
    int tid = threadIdx.x, w = tid >> 5, l = tid & 31;
    size_t mb = (size_t)b * NQ * NQ;
    const float* __restrict__ adjb = adj + mb;
    const float* __restrict__ Db = (it == 1) ? nullptr
                                  : (((it & 1) == 0 ? g_D0 : g_D1) + mb);
    float* __restrict__ Ob = (it == 5) ? (acOut + mb)
                             : (((it & 1) ? g_D0 : g_D1) + mb);

    for (int t = tid; t < NQ; t += 256) {
        As[t] = g_A[b * NQ + t];
        Vs[t] = g_uod[b * NQ + t];
    }

    // Phase 1: transposed strip load. Each warp covers 128 j-rows;
    // lane layout: c = l&7 (strip col), jo = l>>3 (0..3 rows per step).
    if (Db) {
        int c = l & 7, jo = l >> 3;
        int jbase = w * 128;
        #pragma unroll 8
        for (int jb = 0; jb < 128; jb += 4) {
            int j = jbase + jb + jo;
            Zt[j * (SW + 1) + c] = Db[(size_t)j * NQ + i0 + c];
        }
    }
    __syncthreads();

    float kw = g_kw[b];
    int i = i0 + w;
    const float* __restrict__ arow = adjb + (size_t)i * NQ;
    const float* __restrict__ drow = Db ? (Db + (size_t)i * NQ) : nullptr;
    float a_i = As[i], v_i = Vs[i];
    float wv_i = kw * v_i;
    float diagv = a_i + 0.5f * wv_i * v_i;

    float z[32];
    float m = -3.4e38f;
    if (Db) {
        #pragma unroll
        for (int t = 0; t < 32; ++t) {
            int j = l + 32 * t;
            float dij = drow[j];
            float dji = Zt[j * (SW + 1) + w];
            float gs = a_i + As[j] + wv_i * Vs[j];
            float zz = arow[j] + dij - MU_C * (2.f * (dij + dji) + gs);
            if (j == i) zz = arow[j] + dij - MU_C * (2.f * dij + diagv);
            z[t] = zz;
            m = fmaxf(m, zz);
        }
    } else {
        #pragma unroll
        for (int t = 0; t < 32; ++t) {
            int j = l + 32 * t;
            float gs = a_i + As[j] + wv_i * Vs[j];
            float zz = arow[j] - MU_C * gs;
            if (j == i) zz = arow[j] - MU_C * diagv;
            z[t] = zz;
            m = fmaxf(m, zz);
        }
    }

    #pragma unroll
    for (int o = 16; o; o >>= 1) m = fmaxf(m, __shfl_xor_sync(0xffffffffu, m, o));

    float ssum = 0.f;
    #pragma unroll
    for (int t = 0; t < 32; ++t) {
        z[t] = __expf(z[t] - m);
        ssum += z[t];
    }
    #pragma unroll
    for (int o = 16; o; o >>= 1) ssum += __shfl_xor_sync(0xffffffffu, ssum, o);
    float rinv = 1.f / ssum;

    float* __restrict__ orow = Ob + (size_t)i * NQ;
    if (it == 5) {
        #pragma unroll
        for (int t = 0; t < 32; ++t) {
            int j = l + 32 * t;
            orow[j] = z[t] * rinv * arow[j];
        }
    } else {
        #pragma unroll
        for (int t = 0; t < 32; ++t) {
            int j = l + 32 * t;
            float a = arow[j];
            orow[j] = fmaf(z[t] * rinv, a, -a);   // softmax*adj - adj
        }
    }
}

extern "C" void kernel_launch(void* const* d_in, const int* in_sizes, int n_in,
                              void* d_out, int out_size) {
    const float* x   = (const float*)d_in[0];
    const float* adj = (const float*)d_in[1];
    const float* s   = (const float*)d_in[2];
    float* out = (float*)d_out;

    // output layout: out[32,2,128] | Ac[32,1024,1024] | out_adj[32,2,2] | mincut | ortho
    const size_t AC_OFF   = (size_t)BN * 2 * FD;                 // 8192
    const size_t OADJ_OFF = AC_OFF + (size_t)BN * NQ * NQ;       // 33562624
    const size_t MC_OFF   = OADJ_OFF + (size_t)BN * 4;           // 33562752

    k1_rows<<<BN * NQ / 8, 256>>>(adj, s);
    k2_rowdots<<<BN * NQ / 8, 256>>>(adj);
    k3_batch<<<BN, 256>>>(out + OADJ_OFF);
    k5_losses<<<1, 32>>>(out + MC_OFF);
    k4_out<<<BN, 512>>>(x, out);

    dim3 g(NQ / SW, BN);
    for (int it = 1; it <= 5; ++it)
        iter_kernel<<<g, 256>>>(adj, it, out + AC_OFF);
}